// round 2
// baseline (speedup 1.0000x reference)
#include <cuda_runtime.h>
#include <math.h>

#define N_NODES 50000
#define N_EDGES 800000
#define IN_DIM 256
#define HID 64
#define HEADS 4
#define NUM_GRAPHS 8
#define NEG_SLOPE 0.2f

// ---------------- scratch (device globals; no allocation) ----------------
__device__ float g_xw1[(size_t)N_NODES * 256];   // x @ W1
__device__ float g_h1 [(size_t)N_NODES * 256];   // elu(layer1 out)
__device__ float g_xw2[(size_t)N_NODES * 64];    // h1 @ W2
__device__ float g_al1[N_NODES * 4];
__device__ float g_ar1[N_NODES * 4];
__device__ float g_al2[N_NODES];
__device__ float g_ar2[N_NODES];
__device__ int   g_deg[N_NODES];
__device__ int   g_rowptr[N_NODES + 1];
__device__ int   g_cursor[N_NODES];
__device__ int   g_csrc[N_EDGES];
__device__ float g_pool[NUM_GRAPHS * HID];
__device__ float g_cnt[NUM_GRAPHS];

__device__ __forceinline__ float leakyf(float x) { return x > 0.f ? x : NEG_SLOPE * x; }
__device__ __forceinline__ float eluf(float x)   { return x > 0.f ? x : expm1f(x); }

// ---------------- CSR build ----------------
__global__ void zero_kernel() {
    int i = blockIdx.x * blockDim.x + threadIdx.x;
    if (i < N_NODES) g_deg[i] = 0;
    if (i < NUM_GRAPHS * HID) g_pool[i] = 0.f;
    if (i < NUM_GRAPHS) g_cnt[i] = 0.f;
}

__global__ void hist_kernel(const int* __restrict__ dst) {
    int i = blockIdx.x * blockDim.x + threadIdx.x;
    if (i < N_EDGES) atomicAdd(&g_deg[dst[i]], 1);
}

__global__ void scan_kernel() {
    __shared__ int sh[1024];
    int t = threadIdx.x;
    const int CH = (N_NODES + 1023) / 1024;
    int b = t * CH;
    int e = b + CH; if (e > N_NODES) e = N_NODES;
    int s = 0;
    for (int i = b; i < e; i++) s += g_deg[i];
    sh[t] = s;
    __syncthreads();
    // inclusive Hillis-Steele scan
    for (int off = 1; off < 1024; off <<= 1) {
        int v = (t >= off) ? sh[t - off] : 0;
        __syncthreads();
        sh[t] += v;
        __syncthreads();
    }
    int run = sh[t] - s;  // exclusive prefix
    for (int i = b; i < e; i++) {
        g_rowptr[i] = run;
        g_cursor[i] = run;
        run += g_deg[i];
    }
    if (t == 1023) g_rowptr[N_NODES] = sh[1023];
}

__global__ void scatter_kernel(const int* __restrict__ src, const int* __restrict__ dst) {
    int i = blockIdx.x * blockDim.x + threadIdx.x;
    if (i < N_EDGES) {
        int d = dst[i];
        int pos = atomicAdd(&g_cursor[d], 1);
        g_csrc[pos] = src[i];
    }
}

// ---------------- SGEMM: C[M,N] = A[M,K] @ B[K,N], row-major ----------------
// outsel: 0 -> g_xw1, 1 -> g_xw2 ; Aext == nullptr -> use g_h1
template<int BM, int BN, int BK, int TM, int TN>
__global__ void sgemm_kernel(const float* __restrict__ Aext, const float* __restrict__ B,
                             int outsel, int M, int N, int K) {
    const float* A = Aext ? Aext : g_h1;
    float* C = (outsel == 0) ? g_xw1 : g_xw2;

    constexpr int THREADS = (BM / TM) * (BN / TN);
    __shared__ float As[BK][BM];
    __shared__ float Bs[BK][BN];

    int tid  = threadIdx.x;
    int tcol = tid % (BN / TN);
    int trow = tid / (BN / TN);
    int m0 = blockIdx.x * BM;
    int n0 = blockIdx.y * BN;

    float acc[TM][TN];
#pragma unroll
    for (int i = 0; i < TM; i++)
#pragma unroll
        for (int j = 0; j < TN; j++) acc[i][j] = 0.f;

    constexpr int AV = BM * BK / 4 / THREADS;
    constexpr int BV = BK * BN / 4 / THREADS;

    for (int k0 = 0; k0 < K; k0 += BK) {
#pragma unroll
        for (int i = 0; i < AV; i++) {
            int v = tid + i * THREADS;
            int kk4 = v % (BK / 4);
            int mm  = v / (BK / 4);
            int row = m0 + mm;
            float4 a;
            if (row < M) a = *(const float4*)(A + (size_t)row * K + k0 + kk4 * 4);
            else a = make_float4(0.f, 0.f, 0.f, 0.f);
            As[kk4 * 4 + 0][mm] = a.x;
            As[kk4 * 4 + 1][mm] = a.y;
            As[kk4 * 4 + 2][mm] = a.z;
            As[kk4 * 4 + 3][mm] = a.w;
        }
#pragma unroll
        for (int i = 0; i < BV; i++) {
            int v = tid + i * THREADS;
            int nn4 = v % (BN / 4);
            int kk  = v / (BN / 4);
            *(float4*)(&Bs[kk][nn4 * 4]) = *(const float4*)(B + (size_t)(k0 + kk) * N + n0 + nn4 * 4);
        }
        __syncthreads();
#pragma unroll
        for (int kk = 0; kk < BK; kk++) {
            float ra[TM], rb[TN];
#pragma unroll
            for (int i = 0; i < TM; i++) ra[i] = As[kk][trow * TM + i];
#pragma unroll
            for (int j = 0; j < TN; j++) rb[j] = Bs[kk][tcol * TN + j];
#pragma unroll
            for (int i = 0; i < TM; i++)
#pragma unroll
                for (int j = 0; j < TN; j++) acc[i][j] += ra[i] * rb[j];
        }
        __syncthreads();
    }

#pragma unroll
    for (int i = 0; i < TM; i++) {
        int row = m0 + trow * TM + i;
        if (row < M) {
#pragma unroll
            for (int j = 0; j < TN; j += 4) {
                float4 o;
                o.x = acc[i][j + 0]; o.y = acc[i][j + 1];
                o.z = acc[i][j + 2]; o.w = acc[i][j + 3];
                *(float4*)(C + (size_t)row * N + n0 + tcol * TN + j) = o;
            }
        }
    }
}

// ---------------- attention coefficients: al[n,h] = sum_c xw[n,h,c]*a_src[h,c] ----------------
template<int H>
__global__ void attn_kernel(const float* __restrict__ asrc, const float* __restrict__ adst) {
    const float* xw = (H == 4) ? g_xw1 : g_xw2;
    float* al = (H == 4) ? g_al1 : g_al2;
    float* ar = (H == 4) ? g_ar1 : g_ar2;

    int w = (blockIdx.x * blockDim.x + threadIdx.x) >> 5;
    if (w >= N_NODES) return;
    int lane = threadIdx.x & 31;
    constexpr int WID = H * 64;   // row width
    constexpr int J = WID / 32;

    float pal[H], par[H];
#pragma unroll
    for (int h = 0; h < H; h++) { pal[h] = 0.f; par[h] = 0.f; }
#pragma unroll
    for (int j = 0; j < J; j++) {
        int ch = lane + 32 * j;
        float v = xw[(size_t)w * WID + ch];
        pal[j >> 1] += v * asrc[ch];
        par[j >> 1] += v * adst[ch];
    }
#pragma unroll
    for (int h = 0; h < H; h++) {
#pragma unroll
        for (int off = 16; off; off >>= 1) {
            pal[h] += __shfl_xor_sync(0xffffffffu, pal[h], off);
            par[h] += __shfl_xor_sync(0xffffffffu, par[h], off);
        }
    }
    if (lane == 0) {
#pragma unroll
        for (int h = 0; h < H; h++) { al[w * H + h] = pal[h]; ar[w * H + h] = par[h]; }
    }
}

// ---------------- layer-1 aggregation: warp per dst node, online softmax ----------------
__global__ void aggregate1_kernel(const float* __restrict__ bias) {
    int w = (blockIdx.x * blockDim.x + threadIdx.x) >> 5;
    if (w >= N_NODES) return;
    int lane = threadIdx.x & 31;
    int hd = lane >> 3;                 // head of this lane's 8 contiguous channels

    float arh = g_ar1[w * 4 + hd];
    float m = leakyf(g_al1[w * 4 + hd] + arh);   // self-loop e
    float s = 1.f;

    const float4* xself = (const float4*)(g_xw1 + (size_t)w * 256) + lane * 2;
    float4 a0 = xself[0], a1 = xself[1];         // self contribution, weight 1

    int p0 = g_rowptr[w], p1 = g_rowptr[w + 1];
    for (int p = p0; p < p1; p++) {
        int src = g_csrc[p];
        float e = leakyf(g_al1[src * 4 + hd] + arh);
        float mn = fmaxf(m, e);
        float r  = __expf(m - mn);
        float wt = __expf(e - mn);
        s = s * r + wt;
        m = mn;
        const float4* x4 = (const float4*)(g_xw1 + (size_t)src * 256) + lane * 2;
        float4 x0 = x4[0], x1 = x4[1];
        a0.x = a0.x * r + wt * x0.x;  a0.y = a0.y * r + wt * x0.y;
        a0.z = a0.z * r + wt * x0.z;  a0.w = a0.w * r + wt * x0.w;
        a1.x = a1.x * r + wt * x1.x;  a1.y = a1.y * r + wt * x1.y;
        a1.z = a1.z * r + wt * x1.z;  a1.w = a1.w * r + wt * x1.w;
    }
    float inv = 1.f / s;
    int cb = lane * 8;
    float4 o0, o1;
    o0.x = eluf(a0.x * inv + bias[cb + 0]);
    o0.y = eluf(a0.y * inv + bias[cb + 1]);
    o0.z = eluf(a0.z * inv + bias[cb + 2]);
    o0.w = eluf(a0.w * inv + bias[cb + 3]);
    o1.x = eluf(a1.x * inv + bias[cb + 4]);
    o1.y = eluf(a1.y * inv + bias[cb + 5]);
    o1.z = eluf(a1.z * inv + bias[cb + 6]);
    o1.w = eluf(a1.w * inv + bias[cb + 7]);
    float4* op = (float4*)(g_h1 + (size_t)w * 256) + lane * 2;
    op[0] = o0;
    op[1] = o1;
}

// ---------------- layer-2 aggregation + pooling atomics ----------------
__global__ void aggregate2_kernel(const float* __restrict__ bias, const int* __restrict__ batch,
                                  float* __restrict__ out) {
    int w = (blockIdx.x * blockDim.x + threadIdx.x) >> 5;
    if (w >= N_NODES) return;
    int lane = threadIdx.x & 31;

    float arh = g_ar2[w];
    float m = leakyf(g_al2[w] + arh);
    float s = 1.f;
    float2 a = ((const float2*)(g_xw2 + (size_t)w * 64))[lane];

    int p0 = g_rowptr[w], p1 = g_rowptr[w + 1];
    for (int p = p0; p < p1; p++) {
        int src = g_csrc[p];
        float e = leakyf(g_al2[src] + arh);
        float mn = fmaxf(m, e);
        float r  = __expf(m - mn);
        float wt = __expf(e - mn);
        s = s * r + wt;
        m = mn;
        float2 x = ((const float2*)(g_xw2 + (size_t)src * 64))[lane];
        a.x = a.x * r + wt * x.x;
        a.y = a.y * r + wt * x.y;
    }
    float inv = 1.f / s;
    float v0 = eluf(a.x * inv + bias[lane * 2 + 0]);
    float v1 = eluf(a.y * inv + bias[lane * 2 + 1]);
    ((float2*)(out + (size_t)w * 64))[lane] = make_float2(v0, v1);

    int b = batch[w];
    atomicAdd(&g_pool[b * 64 + lane * 2 + 0], v0);
    atomicAdd(&g_pool[b * 64 + lane * 2 + 1], v1);
    if (lane == 0) atomicAdd(&g_cnt[b], 1.f);
}

// ---------------- final FC ----------------
__global__ void fc_kernel(const float* __restrict__ fcW, const float* __restrict__ fcb,
                          float* __restrict__ out) {
    int t = threadIdx.x;
    if (t >= NUM_GRAPHS * 2) return;
    int g = t >> 1, k = t & 1;
    float c = fmaxf(g_cnt[g], 1.f);
    float sum = 0.f;
    for (int ch = 0; ch < HID; ch++) sum += g_pool[g * HID + ch] * fcW[ch * 2 + k];
    out[t] = sum / c + fcb[k];
}

// ---------------- launch ----------------
extern "C" void kernel_launch(void* const* d_in, const int* in_sizes, int n_in,
                              void* d_out, int out_size) {
    const float* x      = (const float*)d_in[0];
    const int*   ei     = (const int*)  d_in[1];
    const int*   batch  = (const int*)  d_in[2];
    const float* W1     = (const float*)d_in[3];
    const float* a_src1 = (const float*)d_in[4];
    const float* a_dst1 = (const float*)d_in[5];
    const float* b1     = (const float*)d_in[6];
    const float* W2     = (const float*)d_in[7];
    const float* a_src2 = (const float*)d_in[8];
    const float* a_dst2 = (const float*)d_in[9];
    const float* b2     = (const float*)d_in[10];
    const float* fcW    = (const float*)d_in[11];
    const float* fcb    = (const float*)d_in[12];
    float* out = (float*)d_out;

    const int* src = ei;
    const int* dst = ei + N_EDGES;

    // CSR build (deterministic work each launch; capture-safe)
    zero_kernel<<<(N_NODES + 255) / 256, 256>>>();
    hist_kernel<<<(N_EDGES + 255) / 256, 256>>>(dst);
    scan_kernel<<<1, 1024>>>();
    scatter_kernel<<<(N_EDGES + 255) / 256, 256>>>(src, dst);

    // Layer 1
    dim3 grid1((N_NODES + 127) / 128, (HEADS * HID) / 128);
    sgemm_kernel<128, 128, 16, 8, 8><<<grid1, 256>>>(x, W1, 0, N_NODES, HEADS * HID, IN_DIM);
    attn_kernel<4><<<(N_NODES + 7) / 8, 256>>>(a_src1, a_dst1);
    aggregate1_kernel<<<(N_NODES + 7) / 8, 256>>>(b1);

    // Layer 2
    dim3 grid2((N_NODES + 127) / 128, 1);
    sgemm_kernel<128, 64, 16, 8, 4><<<grid2, 256>>>(nullptr, W2, 1, N_NODES, HID, HEADS * HID);
    attn_kernel<1><<<(N_NODES + 7) / 8, 256>>>(a_src2, a_dst2);
    aggregate2_kernel<<<(N_NODES + 7) / 8, 256>>>(b2, batch, out);

    // Pool + FC
    fc_kernel<<<1, 32>>>(fcW, fcb, out + (size_t)N_NODES * HID);
}

// round 11
// speedup vs baseline: 1.1800x; 1.1800x over previous
#include <cuda_runtime.h>
#include <cuda_bf16.h>
#include <math.h>
#include <stdint.h>

#define N_NODES 50000
#define N_EDGES 800000
#define IN_DIM 256
#define HID 64
#define HEADS 4
#define NUM_GRAPHS 8
#define NEG_SLOPE 0.2f

// ---------------- scratch (device globals; no allocation) ----------------
__device__ float g_xw1[(size_t)N_NODES * 256];   // x @ W1
__device__ float g_h1 [(size_t)N_NODES * 256];   // elu(layer1 out)
__device__ float g_xw2[(size_t)N_NODES * 64];    // h1 @ W2
__device__ float g_al1[N_NODES * 4];
__device__ float g_ar1[N_NODES * 4];
__device__ float g_al2[N_NODES];
__device__ float g_ar2[N_NODES];
__device__ int   g_deg[N_NODES];
__device__ int   g_rowptr[N_NODES + 1];
__device__ int   g_cursor[N_NODES];
__device__ int   g_csrc[N_EDGES];
__device__ float g_pool[NUM_GRAPHS * HID];
__device__ float g_cnt[NUM_GRAPHS];
// pre-split, pre-transposed weights: BT[n][k] (K-major), bf16 hi/lo
__device__ __nv_bfloat16 g_w1t_hi[256 * 256];
__device__ __nv_bfloat16 g_w1t_lo[256 * 256];
__device__ __nv_bfloat16 g_w2t_hi[64 * 256];
__device__ __nv_bfloat16 g_w2t_lo[64 * 256];

__device__ __forceinline__ float leakyf(float x) { return x > 0.f ? x : NEG_SLOPE * x; }
__device__ __forceinline__ float eluf(float x)   { return x > 0.f ? x : expm1f(x); }

// ---------------- mma.sync helpers (arch-neutral PTX, works at compute_103) ----
__device__ __forceinline__ uint32_t smem_u32(const void* p) {
    uint32_t a;
    asm("{ .reg .u64 t; cvta.to.shared.u64 t, %1; cvt.u32.u64 %0, t; }" : "=r"(a) : "l"(p));
    return a;
}
__device__ __forceinline__ void ldsm4(uint32_t* r, uint32_t addr) {
    asm volatile("ldmatrix.sync.aligned.m8n8.x4.shared.b16 {%0,%1,%2,%3}, [%4];"
                 : "=r"(r[0]), "=r"(r[1]), "=r"(r[2]), "=r"(r[3]) : "r"(addr));
}
__device__ __forceinline__ void mma16816(float* c, const uint32_t* a, uint32_t b0, uint32_t b1) {
    asm volatile("mma.sync.aligned.m16n8k16.row.col.f32.bf16.bf16.f32 "
                 "{%0,%1,%2,%3}, {%4,%5,%6,%7}, {%8,%9}, {%0,%1,%2,%3};"
                 : "+f"(c[0]), "+f"(c[1]), "+f"(c[2]), "+f"(c[3])
                 : "r"(a[0]), "r"(a[1]), "r"(a[2]), "r"(a[3]), "r"(b0), "r"(b1));
}

// ---------------- CSR build ----------------
__global__ void zero_kernel() {
    int i = blockIdx.x * blockDim.x + threadIdx.x;
    if (i < N_NODES) g_deg[i] = 0;
    if (i < NUM_GRAPHS * HID) g_pool[i] = 0.f;
    if (i < NUM_GRAPHS) g_cnt[i] = 0.f;
}

__global__ void hist_kernel(const int* __restrict__ dst) {
    int i = blockIdx.x * blockDim.x + threadIdx.x;
    if (i < N_EDGES) atomicAdd(&g_deg[dst[i]], 1);
}

__global__ void scan_kernel() {
    __shared__ int sh[1024];
    int t = threadIdx.x;
    const int CH = (N_NODES + 1023) / 1024;
    int b = t * CH;
    int e = b + CH; if (e > N_NODES) e = N_NODES;
    int s = 0;
    for (int i = b; i < e; i++) s += g_deg[i];
    sh[t] = s;
    __syncthreads();
    for (int off = 1; off < 1024; off <<= 1) {
        int v = (t >= off) ? sh[t - off] : 0;
        __syncthreads();
        sh[t] += v;
        __syncthreads();
    }
    int run = sh[t] - s;
    for (int i = b; i < e; i++) {
        g_rowptr[i] = run;
        g_cursor[i] = run;
        run += g_deg[i];
    }
    if (t == 1023) g_rowptr[N_NODES] = sh[1023];
}

__global__ void scatter_kernel(const int* __restrict__ src, const int* __restrict__ dst) {
    int i = blockIdx.x * blockDim.x + threadIdx.x;
    if (i < N_EDGES) {
        int d = dst[i];
        int pos = atomicAdd(&g_cursor[d], 1);
        g_csrc[pos] = src[i];
    }
}

// ---------------- weight prepass: transpose + bf16 split ----------------
__global__ void prep_w_kernel(const float* __restrict__ W1, const float* __restrict__ W2) {
    int i = blockIdx.x * blockDim.x + threadIdx.x;
    if (i < 256 * 256) {
        int n = i >> 8, k = i & 255;
        float v = W1[k * 256 + n];
        __nv_bfloat16 h = __float2bfloat16(v);
        g_w1t_hi[i] = h;
        g_w1t_lo[i] = __float2bfloat16(v - __bfloat162float(h));
    } else if (i < 256 * 256 + 64 * 256) {
        int j = i - 256 * 256;
        int n = j >> 8, k = j & 255;
        float v = W2[k * 64 + n];
        __nv_bfloat16 h = __float2bfloat16(v);
        g_w2t_hi[j] = h;
        g_w2t_lo[j] = __float2bfloat16(v - __bfloat162float(h));
    }
}

// ---------------- split-bf16 tensor-core GEMM via mma.sync ----------------
// C[M,NTOT] = A[M,256] @ W[256,NTOT]; W pre-transposed/split as [NTOT][256] hi/lo.
// CTA tile 128x64, BK=32, 8 warps (4 m x 2 n), warp tile 32x32.
// A source selected INSIDE the kernel (device symbol illegal as host-side arg).
#define PAD 20   // u32 per smem row (16 used + 4 pad) -> conflict-free ldmatrix

template<int NTOT>
__global__ void __launch_bounds__(256, 2) gemm_mma_kernel(const float* __restrict__ Aext, int M) {
    const float* A = (NTOT == 256) ? Aext : g_h1;   // layer 2 reads g_h1
    const uint32_t* Bh32 = (const uint32_t*)((NTOT == 256) ? g_w1t_hi : g_w2t_hi);
    const uint32_t* Bl32 = (const uint32_t*)((NTOT == 256) ? g_w1t_lo : g_w2t_lo);
    float* C = (NTOT == 256) ? g_xw1 : g_xw2;

    __shared__ __align__(16) uint32_t sAhi[128 * PAD], sAlo[128 * PAD];
    __shared__ __align__(16) uint32_t sBhi[64 * PAD],  sBlo[64 * PAD];

    int tid = threadIdx.x, lane = tid & 31, wid = tid >> 5;
    int wm = wid >> 1, wn = wid & 1;
    int m0 = blockIdx.x * 128;
    int n0 = blockIdx.y * 64;

    uint32_t aHiB = smem_u32(sAhi), aLoB = smem_u32(sAlo);
    uint32_t bHiB = smem_u32(sBhi), bLoB = smem_u32(sBlo);

    float acc[2][4][4];
#pragma unroll
    for (int am = 0; am < 2; am++)
#pragma unroll
        for (int bn = 0; bn < 4; bn++)
#pragma unroll
            for (int q = 0; q < 4; q++) acc[am][bn][q] = 0.f;

    // precomputed ldmatrix lane addresses (byte offsets into smem arrays)
    uint32_t aoff[2];
#pragma unroll
    for (int am = 0; am < 2; am++) {
        int rowm = wm * 32 + am * 16 + (lane & 15);
        aoff[am] = (uint32_t)(rowm * PAD + (lane >> 4) * 4) * 4;
    }
    int rowbA = wn * 32 + ((lane >> 4) & 1) * 8 + (lane & 7);
    uint32_t boff[2];
#pragma unroll
    for (int bp = 0; bp < 2; bp++)
        boff[bp] = (uint32_t)((rowbA + bp * 16) * PAD + ((lane >> 3) & 1) * 4) * 4;

    for (int kc = 0; kc < 8; kc++) {       // K=256 in chunks of 32
        // ---- fill A chunk: 128 x 32 fp32 -> bf16 hi/lo ----
#pragma unroll
        for (int i = 0; i < 4; i++) {
            int v = tid + i * 256;
            int r = v >> 3, c4 = v & 7;
            int row = m0 + r; if (row >= M) row = M - 1;
            float4 f = *(const float4*)(A + (size_t)row * 256 + kc * 32 + c4 * 4);
            __nv_bfloat162 h0, h1, l0, l1;
            h0.x = __float2bfloat16(f.x); h0.y = __float2bfloat16(f.y);
            h1.x = __float2bfloat16(f.z); h1.y = __float2bfloat16(f.w);
            l0.x = __float2bfloat16(f.x - __bfloat162float(h0.x));
            l0.y = __float2bfloat16(f.y - __bfloat162float(h0.y));
            l1.x = __float2bfloat16(f.z - __bfloat162float(h1.x));
            l1.y = __float2bfloat16(f.w - __bfloat162float(h1.y));
            sAhi[r * PAD + c4 * 2 + 0] = *(uint32_t*)&h0;
            sAhi[r * PAD + c4 * 2 + 1] = *(uint32_t*)&h1;
            sAlo[r * PAD + c4 * 2 + 0] = *(uint32_t*)&l0;
            sAlo[r * PAD + c4 * 2 + 1] = *(uint32_t*)&l1;
        }
        // ---- fill B chunk: 64 x 32 bf16 hi/lo (pre-split, [NTOT][256]) ----
#pragma unroll
        for (int i = 0; i < 4; i++) {
            int v = tid + i * 256;
            int r = v >> 4, c = v & 15;
            uint32_t g = (uint32_t)(n0 + r) * 128 + kc * 16 + c;
            sBhi[r * PAD + c] = Bh32[g];
            sBlo[r * PAD + c] = Bl32[g];
        }
        __syncthreads();

        // ---- 2 k16 steps ----
#pragma unroll
        for (int ks = 0; ks < 2; ks++) {
            uint32_t ahi[2][4], alo[2][4], bhi[2][4], blo[2][4];
            uint32_t kb = (uint32_t)(ks * 8 * 4);
#pragma unroll
            for (int am = 0; am < 2; am++) {
                ldsm4(ahi[am], aHiB + aoff[am] + kb);
                ldsm4(alo[am], aLoB + aoff[am] + kb);
            }
#pragma unroll
            for (int bp = 0; bp < 2; bp++) {
                ldsm4(bhi[bp], bHiB + boff[bp] + kb);
                ldsm4(blo[bp], bLoB + boff[bp] + kb);
            }
#pragma unroll
            for (int am = 0; am < 2; am++)
#pragma unroll
                for (int bp = 0; bp < 2; bp++)
#pragma unroll
                    for (int h = 0; h < 2; h++) {
                        float* c = acc[am][bp * 2 + h];
                        mma16816(c, ahi[am], bhi[bp][h * 2], bhi[bp][h * 2 + 1]);
                        mma16816(c, ahi[am], blo[bp][h * 2], blo[bp][h * 2 + 1]);
                        mma16816(c, alo[am], bhi[bp][h * 2], bhi[bp][h * 2 + 1]);
                    }
        }
        __syncthreads();
    }

    // ---- epilogue: write C ----
    int gr = lane >> 2;
    int gc = (lane & 3) * 2;
#pragma unroll
    for (int am = 0; am < 2; am++) {
        int row0 = m0 + wm * 32 + am * 16 + gr;
#pragma unroll
        for (int bn = 0; bn < 4; bn++) {
            int col = n0 + wn * 32 + bn * 8 + gc;
            if (row0 < M)
                *(float2*)(C + (size_t)row0 * NTOT + col) = make_float2(acc[am][bn][0], acc[am][bn][1]);
            if (row0 + 8 < M)
                *(float2*)(C + (size_t)(row0 + 8) * NTOT + col) = make_float2(acc[am][bn][2], acc[am][bn][3]);
        }
    }
}

// ---------------- attention coefficients ----------------
template<int H>
__global__ void attn_kernel(const float* __restrict__ asrc, const float* __restrict__ adst) {
    const float* xw = (H == 4) ? g_xw1 : g_xw2;
    float* al = (H == 4) ? g_al1 : g_al2;
    float* ar = (H == 4) ? g_ar1 : g_ar2;

    int w = (blockIdx.x * blockDim.x + threadIdx.x) >> 5;
    if (w >= N_NODES) return;
    int lane = threadIdx.x & 31;
    constexpr int WID = H * 64;
    constexpr int J = WID / 32;

    float pal[H], par[H];
#pragma unroll
    for (int h = 0; h < H; h++) { pal[h] = 0.f; par[h] = 0.f; }
#pragma unroll
    for (int j = 0; j < J; j++) {
        int ch = lane + 32 * j;
        float v = xw[(size_t)w * WID + ch];
        pal[j >> 1] += v * asrc[ch];
        par[j >> 1] += v * adst[ch];
    }
#pragma unroll
    for (int h = 0; h < H; h++) {
#pragma unroll
        for (int off = 16; off; off >>= 1) {
            pal[h] += __shfl_xor_sync(0xffffffffu, pal[h], off);
            par[h] += __shfl_xor_sync(0xffffffffu, par[h], off);
        }
    }
    if (lane == 0) {
#pragma unroll
        for (int h = 0; h < H; h++) { al[w * H + h] = pal[h]; ar[w * H + h] = par[h]; }
    }
}

// ---------------- layer-1 aggregation: warp per dst node, online softmax ----------------
__global__ void aggregate1_kernel(const float* __restrict__ bias) {
    int w = (blockIdx.x * blockDim.x + threadIdx.x) >> 5;
    if (w >= N_NODES) return;
    int lane = threadIdx.x & 31;
    int hd = lane >> 3;

    float arh = g_ar1[w * 4 + hd];
    float m = leakyf(g_al1[w * 4 + hd] + arh);
    float s = 1.f;

    const float4* xself = (const float4*)(g_xw1 + (size_t)w * 256) + lane * 2;
    float4 a0 = xself[0], a1 = xself[1];

    int p0 = g_rowptr[w], p1 = g_rowptr[w + 1];
    for (int p = p0; p < p1; p++) {
        int src = g_csrc[p];
        float e = leakyf(g_al1[src * 4 + hd] + arh);
        float mn = fmaxf(m, e);
        float r  = __expf(m - mn);
        float wt = __expf(e - mn);
        s = s * r + wt;
        m = mn;
        const float4* x4 = (const float4*)(g_xw1 + (size_t)src * 256) + lane * 2;
        float4 x0 = x4[0], x1 = x4[1];
        a0.x = a0.x * r + wt * x0.x;  a0.y = a0.y * r + wt * x0.y;
        a0.z = a0.z * r + wt * x0.z;  a0.w = a0.w * r + wt * x0.w;
        a1.x = a1.x * r + wt * x1.x;  a1.y = a1.y * r + wt * x1.y;
        a1.z = a1.z * r + wt * x1.z;  a1.w = a1.w * r + wt * x1.w;
    }
    float inv = 1.f / s;
    int cb = lane * 8;
    float4 o0, o1;
    o0.x = eluf(a0.x * inv + bias[cb + 0]);
    o0.y = eluf(a0.y * inv + bias[cb + 1]);
    o0.z = eluf(a0.z * inv + bias[cb + 2]);
    o0.w = eluf(a0.w * inv + bias[cb + 3]);
    o1.x = eluf(a1.x * inv + bias[cb + 4]);
    o1.y = eluf(a1.y * inv + bias[cb + 5]);
    o1.z = eluf(a1.z * inv + bias[cb + 6]);
    o1.w = eluf(a1.w * inv + bias[cb + 7]);
    float4* op = (float4*)(g_h1 + (size_t)w * 256) + lane * 2;
    op[0] = o0;
    op[1] = o1;
}

// ---------------- layer-2 aggregation + pooling atomics ----------------
__global__ void aggregate2_kernel(const float* __restrict__ bias, const int* __restrict__ batch,
                                  float* __restrict__ out) {
    int w = (blockIdx.x * blockDim.x + threadIdx.x) >> 5;
    if (w >= N_NODES) return;
    int lane = threadIdx.x & 31;

    float arh = g_ar2[w];
    float m = leakyf(g_al2[w] + arh);
    float s = 1.f;
    float2 a = ((const float2*)(g_xw2 + (size_t)w * 64))[lane];

    int p0 = g_rowptr[w], p1 = g_rowptr[w + 1];
    for (int p = p0; p < p1; p++) {
        int src = g_csrc[p];
        float e = leakyf(g_al2[src] + arh);
        float mn = fmaxf(m, e);
        float r  = __expf(m - mn);
        float wt = __expf(e - mn);
        s = s * r + wt;
        m = mn;
        float2 x = ((const float2*)(g_xw2 + (size_t)src * 64))[lane];
        a.x = a.x * r + wt * x.x;
        a.y = a.y * r + wt * x.y;
    }
    float inv = 1.f / s;
    float v0 = eluf(a.x * inv + bias[lane * 2 + 0]);
    float v1 = eluf(a.y * inv + bias[lane * 2 + 1]);
    ((float2*)(out + (size_t)w * 64))[lane] = make_float2(v0, v1);

    int b = batch[w];
    atomicAdd(&g_pool[b * 64 + lane * 2 + 0], v0);
    atomicAdd(&g_pool[b * 64 + lane * 2 + 1], v1);
    if (lane == 0) atomicAdd(&g_cnt[b], 1.f);
}

// ---------------- final FC ----------------
__global__ void fc_kernel(const float* __restrict__ fcW, const float* __restrict__ fcb,
                          float* __restrict__ out) {
    int t = threadIdx.x;
    if (t >= NUM_GRAPHS * 2) return;
    int g = t >> 1, k = t & 1;
    float c = fmaxf(g_cnt[g], 1.f);
    float sum = 0.f;
    for (int ch = 0; ch < HID; ch++) sum += g_pool[g * HID + ch] * fcW[ch * 2 + k];
    out[t] = sum / c + fcb[k];
}

// ---------------- launch ----------------
extern "C" void kernel_launch(void* const* d_in, const int* in_sizes, int n_in,
                              void* d_out, int out_size) {
    const float* x      = (const float*)d_in[0];
    const int*   ei     = (const int*)  d_in[1];
    const int*   batch  = (const int*)  d_in[2];
    const float* W1     = (const float*)d_in[3];
    const float* a_src1 = (const float*)d_in[4];
    const float* a_dst1 = (const float*)d_in[5];
    const float* b1     = (const float*)d_in[6];
    const float* W2     = (const float*)d_in[7];
    const float* a_src2 = (const float*)d_in[8];
    const float* a_dst2 = (const float*)d_in[9];
    const float* b2     = (const float*)d_in[10];
    const float* fcW    = (const float*)d_in[11];
    const float* fcb    = (const float*)d_in[12];
    float* out = (float*)d_out;

    const int* src = ei;
    const int* dst = ei + N_EDGES;

    const int NBLK = (N_NODES + 127) / 128;   // 391

    // weight prepass + CSR build
    prep_w_kernel<<<(256 * 256 + 64 * 256 + 255) / 256, 256>>>(W1, W2);
    zero_kernel<<<(N_NODES + 255) / 256, 256>>>();
    hist_kernel<<<(N_EDGES + 255) / 256, 256>>>(dst);
    scan_kernel<<<1, 1024>>>();
    scatter_kernel<<<(N_EDGES + 255) / 256, 256>>>(src, dst);

    // Layer 1: tensor-core GEMM (mma.sync bf16 split), attention dots, aggregation
    dim3 grid1(NBLK, 4);
    gemm_mma_kernel<256><<<grid1, 256>>>(x, N_NODES);
    attn_kernel<4><<<(N_NODES + 7) / 8, 256>>>(a_src1, a_dst1);
    aggregate1_kernel<<<(N_NODES + 7) / 8, 256>>>(b1);

    // Layer 2 (A = g_h1 selected inside the kernel)
    dim3 grid2(NBLK, 1);
    gemm_mma_kernel<64><<<grid2, 256>>>(nullptr, N_NODES);
    attn_kernel<1><<<(N_NODES + 7) / 8, 256>>>(a_src2, a_dst2);
    aggregate2_kernel<<<(N_NODES + 7) / 8, 256>>>(b2, batch, out);

    // Pool + FC
    fc_kernel<<<1, 32>>>(fcW, fcb, out + (size_t)N_NODES * HID);
}

// round 14
// speedup vs baseline: 1.3504x; 1.1444x over previous
#include <cuda_runtime.h>
#include <cuda_bf16.h>
#include <math.h>
#include <stdint.h>

#define N_NODES 50000
#define N_EDGES 800000
#define IN_DIM 256
#define HID 64
#define HEADS 4
#define NUM_GRAPHS 8
#define NEG_SLOPE 0.2f
#define SCAN_BLOCKS 49   // 49*1024 >= 50000

// ---------------- scratch (device globals; no allocation) ----------------
__device__ float g_xw1[(size_t)N_NODES * 256];   // x @ W1
__device__ float g_h1 [(size_t)N_NODES * 256];   // elu(layer1 out)
__device__ float g_xw2[(size_t)N_NODES * 64];    // h1 @ W2
__device__ float g_al1[N_NODES * 4];
__device__ float g_ar1[N_NODES * 4];
__device__ float g_al2[N_NODES];
__device__ float g_ar2[N_NODES];
__device__ int   g_deg[N_NODES];
__device__ int   g_rowptr[N_NODES + 1];
__device__ int   g_cursor[N_NODES];
__device__ int   g_csrc[N_EDGES];
__device__ int   g_bsum[SCAN_BLOCKS];
__device__ int   g_boff[SCAN_BLOCKS + 1];
__device__ float g_pool[NUM_GRAPHS * HID];
__device__ float g_cnt[NUM_GRAPHS];
// pre-split, pre-transposed weights: BT[n][k] (K-major), bf16 hi/lo
__device__ __nv_bfloat16 g_w1t_hi[256 * 256];
__device__ __nv_bfloat16 g_w1t_lo[256 * 256];
__device__ __nv_bfloat16 g_w2t_hi[64 * 256];
__device__ __nv_bfloat16 g_w2t_lo[64 * 256];

__device__ __forceinline__ float leakyf(float x) { return x > 0.f ? x : NEG_SLOPE * x; }
__device__ __forceinline__ float eluf(float x)   { return x > 0.f ? x : expm1f(x); }

// ---------------- mma.sync helpers (arch-neutral PTX, works at compute_103) ----
__device__ __forceinline__ uint32_t smem_u32(const void* p) {
    uint32_t a;
    asm("{ .reg .u64 t; cvta.to.shared.u64 t, %1; cvt.u32.u64 %0, t; }" : "=r"(a) : "l"(p));
    return a;
}
__device__ __forceinline__ void ldsm4(uint32_t* r, uint32_t addr) {
    asm volatile("ldmatrix.sync.aligned.m8n8.x4.shared.b16 {%0,%1,%2,%3}, [%4];"
                 : "=r"(r[0]), "=r"(r[1]), "=r"(r[2]), "=r"(r[3]) : "r"(addr));
}
__device__ __forceinline__ void mma16816(float* c, const uint32_t* a, uint32_t b0, uint32_t b1) {
    asm volatile("mma.sync.aligned.m16n8k16.row.col.f32.bf16.bf16.f32 "
                 "{%0,%1,%2,%3}, {%4,%5,%6,%7}, {%8,%9}, {%0,%1,%2,%3};"
                 : "+f"(c[0]), "+f"(c[1]), "+f"(c[2]), "+f"(c[3])
                 : "r"(a[0]), "r"(a[1]), "r"(a[2]), "r"(a[3]), "r"(b0), "r"(b1));
}

// ---------------- zero / CSR build ----------------
__global__ void zero_kernel() {
    int i = blockIdx.x * blockDim.x + threadIdx.x;
    if (i < N_NODES) g_deg[i] = 0;
    if (i < N_NODES * 4) { g_al1[i] = 0.f; g_ar1[i] = 0.f; }
    if (i < N_NODES)     { g_al2[i] = 0.f; g_ar2[i] = 0.f; }
    if (i < NUM_GRAPHS * HID) g_pool[i] = 0.f;
    if (i < NUM_GRAPHS) g_cnt[i] = 0.f;
}

__global__ void hist_kernel(const int* __restrict__ dst) {
    int i = blockIdx.x * blockDim.x + threadIdx.x;
    if (i < N_EDGES) atomicAdd(&g_deg[dst[i]], 1);
}

// parallel scan: phase 1 — per-block exclusive scan + block sums
__global__ void scan1_kernel() {
    __shared__ int sh[1024];
    int t = threadIdx.x;
    int gid = blockIdx.x * 1024 + t;
    int v = (gid < N_NODES) ? g_deg[gid] : 0;
    sh[t] = v;
    __syncthreads();
    for (int off = 1; off < 1024; off <<= 1) {
        int u = (t >= off) ? sh[t - off] : 0;
        __syncthreads();
        sh[t] += u;
        __syncthreads();
    }
    if (gid < N_NODES) g_rowptr[gid] = sh[t] - v;     // local exclusive
    if (t == 1023) g_bsum[blockIdx.x] = sh[1023];
}

// phase 2 — scan 49 block sums (trivial)
__global__ void scan2_kernel() {
    if (threadIdx.x == 0) {
        int run = 0;
        for (int b = 0; b < SCAN_BLOCKS; b++) {
            g_boff[b] = run;
            run += g_bsum[b];
        }
        g_boff[SCAN_BLOCKS] = run;
        g_rowptr[N_NODES] = run;
    }
}

// phase 3 — apply block offsets
__global__ void scan3_kernel() {
    int t = threadIdx.x;
    int gid = blockIdx.x * 1024 + t;
    if (gid < N_NODES) {
        int r = g_rowptr[gid] + g_boff[blockIdx.x];
        g_rowptr[gid] = r;
        g_cursor[gid] = r;
    }
}

__global__ void scatter_kernel(const int* __restrict__ src, const int* __restrict__ dst) {
    int i = blockIdx.x * blockDim.x + threadIdx.x;
    if (i < N_EDGES) {
        int d = dst[i];
        int pos = atomicAdd(&g_cursor[d], 1);
        g_csrc[pos] = src[i];
    }
}

// ---------------- weight prepass: transpose + bf16 split ----------------
__global__ void prep_w_kernel(const float* __restrict__ W1, const float* __restrict__ W2) {
    int i = blockIdx.x * blockDim.x + threadIdx.x;
    if (i < 256 * 256) {
        int n = i >> 8, k = i & 255;
        float v = W1[k * 256 + n];
        __nv_bfloat16 h = __float2bfloat16(v);
        g_w1t_hi[i] = h;
        g_w1t_lo[i] = __float2bfloat16(v - __bfloat162float(h));
    } else if (i < 256 * 256 + 64 * 256) {
        int j = i - 256 * 256;
        int n = j >> 8, k = j & 255;
        float v = W2[k * 64 + n];
        __nv_bfloat16 h = __float2bfloat16(v);
        g_w2t_hi[j] = h;
        g_w2t_lo[j] = __float2bfloat16(v - __bfloat162float(h));
    }
}

// ---------------- split-bf16 tensor-core GEMM via mma.sync ----------------
// C[M,NTOT] = A[M,256] @ W[256,NTOT]; W pre-transposed/split as [NTOT][256] hi/lo.
// CTA tile 128x64, BK=32, 8 warps (4 m x 2 n), warp tile 32x32.
// Fused: attention dots al/ar accumulated via quad-reduce + atomicAdd.
#define PAD 20   // u32 per smem row (16 used + 4 pad) -> conflict-free ldmatrix

template<int NTOT>
__global__ void __launch_bounds__(256, 2) gemm_mma_kernel(
    const float* __restrict__ Aext,
    const float* __restrict__ asrc, const float* __restrict__ adst, int M)
{
    const float* A = (NTOT == 256) ? Aext : g_h1;   // layer 2 reads g_h1
    const uint32_t* Bh32 = (const uint32_t*)((NTOT == 256) ? g_w1t_hi : g_w2t_hi);
    const uint32_t* Bl32 = (const uint32_t*)((NTOT == 256) ? g_w1t_lo : g_w2t_lo);
    float* C  = (NTOT == 256) ? g_xw1 : g_xw2;
    float* AL = (NTOT == 256) ? g_al1 : g_al2;
    float* AR = (NTOT == 256) ? g_ar1 : g_ar2;
    constexpr int H = NTOT / 64;        // heads in this layer

    __shared__ __align__(16) uint32_t sAhi[128 * PAD], sAlo[128 * PAD];
    __shared__ __align__(16) uint32_t sBhi[64 * PAD],  sBlo[64 * PAD];

    int tid = threadIdx.x, lane = tid & 31, wid = tid >> 5;
    int wm = wid >> 1, wn = wid & 1;
    int m0 = blockIdx.x * 128;
    int n0 = blockIdx.y * 64;
    int hd = blockIdx.y;                // head index (NTOT=256) or 0

    // per-head attention vectors (a_src is [H, 64])
    const float* as = asrc + hd * 64;
    const float* ad = adst + hd * 64;

    uint32_t aHiB = smem_u32(sAhi), aLoB = smem_u32(sAlo);
    uint32_t bHiB = smem_u32(sBhi), bLoB = smem_u32(sBlo);

    float acc[2][4][4];
#pragma unroll
    for (int am = 0; am < 2; am++)
#pragma unroll
        for (int bn = 0; bn < 4; bn++)
#pragma unroll
            for (int q = 0; q < 4; q++) acc[am][bn][q] = 0.f;

    uint32_t aoff[2];
#pragma unroll
    for (int am = 0; am < 2; am++) {
        int rowm = wm * 32 + am * 16 + (lane & 15);
        aoff[am] = (uint32_t)(rowm * PAD + (lane >> 4) * 4) * 4;
    }
    int rowbA = wn * 32 + ((lane >> 4) & 1) * 8 + (lane & 7);
    uint32_t boff[2];
#pragma unroll
    for (int bp = 0; bp < 2; bp++)
        boff[bp] = (uint32_t)((rowbA + bp * 16) * PAD + ((lane >> 3) & 1) * 4) * 4;

    for (int kc = 0; kc < 8; kc++) {       // K=256 in chunks of 32
#pragma unroll
        for (int i = 0; i < 4; i++) {
            int v = tid + i * 256;
            int r = v >> 3, c4 = v & 7;
            int row = m0 + r; if (row >= M) row = M - 1;
            float4 f = *(const float4*)(A + (size_t)row * 256 + kc * 32 + c4 * 4);
            __nv_bfloat162 h0, h1, l0, l1;
            h0.x = __float2bfloat16(f.x); h0.y = __float2bfloat16(f.y);
            h1.x = __float2bfloat16(f.z); h1.y = __float2bfloat16(f.w);
            l0.x = __float2bfloat16(f.x - __bfloat162float(h0.x));
            l0.y = __float2bfloat16(f.y - __bfloat162float(h0.y));
            l1.x = __float2bfloat16(f.z - __bfloat162float(h1.x));
            l1.y = __float2bfloat16(f.w - __bfloat162float(h1.y));
            sAhi[r * PAD + c4 * 2 + 0] = *(uint32_t*)&h0;
            sAhi[r * PAD + c4 * 2 + 1] = *(uint32_t*)&h1;
            sAlo[r * PAD + c4 * 2 + 0] = *(uint32_t*)&l0;
            sAlo[r * PAD + c4 * 2 + 1] = *(uint32_t*)&l1;
        }
#pragma unroll
        for (int i = 0; i < 4; i++) {
            int v = tid + i * 256;
            int r = v >> 4, c = v & 15;
            uint32_t g = (uint32_t)(n0 + r) * 128 + kc * 16 + c;
            sBhi[r * PAD + c] = Bh32[g];
            sBlo[r * PAD + c] = Bl32[g];
        }
        __syncthreads();

#pragma unroll
        for (int ks = 0; ks < 2; ks++) {
            uint32_t ahi[2][4], alo[2][4], bhi[2][4], blo[2][4];
            uint32_t kb = (uint32_t)(ks * 8 * 4);
#pragma unroll
            for (int am = 0; am < 2; am++) {
                ldsm4(ahi[am], aHiB + aoff[am] + kb);
                ldsm4(alo[am], aLoB + aoff[am] + kb);
            }
#pragma unroll
            for (int bp = 0; bp < 2; bp++) {
                ldsm4(bhi[bp], bHiB + boff[bp] + kb);
                ldsm4(blo[bp], bLoB + boff[bp] + kb);
            }
#pragma unroll
            for (int am = 0; am < 2; am++)
#pragma unroll
                for (int bp = 0; bp < 2; bp++)
#pragma unroll
                    for (int h = 0; h < 2; h++) {
                        float* c = acc[am][bp * 2 + h];
                        mma16816(c, ahi[am], bhi[bp][h * 2], bhi[bp][h * 2 + 1]);
                        mma16816(c, ahi[am], blo[bp][h * 2], blo[bp][h * 2 + 1]);
                        mma16816(c, alo[am], bhi[bp][h * 2], bhi[bp][h * 2 + 1]);
                    }
        }
        __syncthreads();
    }

    // ---- epilogue: write C + fused attention dots ----
    int gr = lane >> 2;
    int gc = (lane & 3) * 2;
#pragma unroll
    for (int am = 0; am < 2; am++) {
        int row0 = m0 + wm * 32 + am * 16 + gr;
        float pal0 = 0.f, par0 = 0.f, pal1 = 0.f, par1 = 0.f;
#pragma unroll
        for (int bn = 0; bn < 4; bn++) {
            int c = wn * 32 + bn * 8 + gc;          // column within head
            float s0 = as[c], s1 = as[c + 1];
            float d0 = ad[c], d1 = ad[c + 1];
            pal0 += acc[am][bn][0] * s0 + acc[am][bn][1] * s1;
            par0 += acc[am][bn][0] * d0 + acc[am][bn][1] * d1;
            pal1 += acc[am][bn][2] * s0 + acc[am][bn][3] * s1;
            par1 += acc[am][bn][2] * d0 + acc[am][bn][3] * d1;

            int col = n0 + c;
            if (row0 < M)
                *(float2*)(C + (size_t)row0 * NTOT + col) = make_float2(acc[am][bn][0], acc[am][bn][1]);
            if (row0 + 8 < M)
                *(float2*)(C + (size_t)(row0 + 8) * NTOT + col) = make_float2(acc[am][bn][2], acc[am][bn][3]);
        }
        // quad reduce (lanes sharing gr differ only in lane&3)
#pragma unroll
        for (int off = 1; off <= 2; off <<= 1) {
            pal0 += __shfl_xor_sync(0xffffffffu, pal0, off);
            par0 += __shfl_xor_sync(0xffffffffu, par0, off);
            pal1 += __shfl_xor_sync(0xffffffffu, pal1, off);
            par1 += __shfl_xor_sync(0xffffffffu, par1, off);
        }
        if ((lane & 3) == 0) {
            if (row0 < M) {
                atomicAdd(&AL[row0 * H + hd], pal0);
                atomicAdd(&AR[row0 * H + hd], par0);
            }
            if (row0 + 8 < M) {
                atomicAdd(&AL[(row0 + 8) * H + hd], pal1);
                atomicAdd(&AR[(row0 + 8) * H + hd], par1);
            }
        }
    }
}

// ---------------- layer-1 aggregation: warp per dst node, online softmax ----------------
__global__ void aggregate1_kernel(const float* __restrict__ bias) {
    int w = (blockIdx.x * blockDim.x + threadIdx.x) >> 5;
    if (w >= N_NODES) return;
    int lane = threadIdx.x & 31;
    int hd = lane >> 3;

    float arh = g_ar1[w * 4 + hd];
    float m = leakyf(g_al1[w * 4 + hd] + arh);
    float s = 1.f;

    const float4* xself = (const float4*)(g_xw1 + (size_t)w * 256) + lane * 2;
    float4 a0 = xself[0], a1 = xself[1];

    int p0 = g_rowptr[w], p1 = g_rowptr[w + 1];
    for (int p = p0; p < p1; p++) {
        int src = g_csrc[p];
        float e = leakyf(g_al1[src * 4 + hd] + arh);
        float mn = fmaxf(m, e);
        float r  = __expf(m - mn);
        float wt = __expf(e - mn);
        s = s * r + wt;
        m = mn;
        const float4* x4 = (const float4*)(g_xw1 + (size_t)src * 256) + lane * 2;
        float4 x0 = x4[0], x1 = x4[1];
        a0.x = a0.x * r + wt * x0.x;  a0.y = a0.y * r + wt * x0.y;
        a0.z = a0.z * r + wt * x0.z;  a0.w = a0.w * r + wt * x0.w;
        a1.x = a1.x * r + wt * x1.x;  a1.y = a1.y * r + wt * x1.y;
        a1.z = a1.z * r + wt * x1.z;  a1.w = a1.w * r + wt * x1.w;
    }
    float inv = 1.f / s;
    int cb = lane * 8;
    float4 o0, o1;
    o0.x = eluf(a0.x * inv + bias[cb + 0]);
    o0.y = eluf(a0.y * inv + bias[cb + 1]);
    o0.z = eluf(a0.z * inv + bias[cb + 2]);
    o0.w = eluf(a0.w * inv + bias[cb + 3]);
    o1.x = eluf(a1.x * inv + bias[cb + 4]);
    o1.y = eluf(a1.y * inv + bias[cb + 5]);
    o1.z = eluf(a1.z * inv + bias[cb + 6]);
    o1.w = eluf(a1.w * inv + bias[cb + 7]);
    float4* op = (float4*)(g_h1 + (size_t)w * 256) + lane * 2;
    op[0] = o0;
    op[1] = o1;
}

// ---------------- layer-2 aggregation + pooling atomics ----------------
__global__ void aggregate2_kernel(const float* __restrict__ bias, const int* __restrict__ batch,
                                  float* __restrict__ out) {
    int w = (blockIdx.x * blockDim.x + threadIdx.x) >> 5;
    if (w >= N_NODES) return;
    int lane = threadIdx.x & 31;

    float arh = g_ar2[w];
    float m = leakyf(g_al2[w] + arh);
    float s = 1.f;
    float2 a = ((const float2*)(g_xw2 + (size_t)w * 64))[lane];

    int p0 = g_rowptr[w], p1 = g_rowptr[w + 1];
    for (int p = p0; p < p1; p++) {
        int src = g_csrc[p];
        float e = leakyf(g_al2[src] + arh);
        float mn = fmaxf(m, e);
        float r  = __expf(m - mn);
        float wt = __expf(e - mn);
        s = s * r + wt;
        m = mn;
        float2 x = ((const float2*)(g_xw2 + (size_t)src * 64))[lane];
        a.x = a.x * r + wt * x.x;
        a.y = a.y * r + wt * x.y;
    }
    float inv = 1.f / s;
    float v0 = eluf(a.x * inv + bias[lane * 2 + 0]);
    float v1 = eluf(a.y * inv + bias[lane * 2 + 1]);
    ((float2*)(out + (size_t)w * 64))[lane] = make_float2(v0, v1);

    int b = batch[w];
    atomicAdd(&g_pool[b * 64 + lane * 2 + 0], v0);
    atomicAdd(&g_pool[b * 64 + lane * 2 + 1], v1);
    if (lane == 0) atomicAdd(&g_cnt[b], 1.f);
}

// ---------------- final FC ----------------
__global__ void fc_kernel(const float* __restrict__ fcW, const float* __restrict__ fcb,
                          float* __restrict__ out) {
    int t = threadIdx.x;
    if (t >= NUM_GRAPHS * 2) return;
    int g = t >> 1, k = t & 1;
    float c = fmaxf(g_cnt[g], 1.f);
    float sum = 0.f;
    for (int ch = 0; ch < HID; ch++) sum += g_pool[g * HID + ch] * fcW[ch * 2 + k];
    out[t] = sum / c + fcb[k];
}

// ---------------- launch ----------------
extern "C" void kernel_launch(void* const* d_in, const int* in_sizes, int n_in,
                              void* d_out, int out_size) {
    const float* x      = (const float*)d_in[0];
    const int*   ei     = (const int*)  d_in[1];
    const int*   batch  = (const int*)  d_in[2];
    const float* W1     = (const float*)d_in[3];
    const float* a_src1 = (const float*)d_in[4];
    const float* a_dst1 = (const float*)d_in[5];
    const float* b1     = (const float*)d_in[6];
    const float* W2     = (const float*)d_in[7];
    const float* a_src2 = (const float*)d_in[8];
    const float* a_dst2 = (const float*)d_in[9];
    const float* b2     = (const float*)d_in[10];
    const float* fcW    = (const float*)d_in[11];
    const float* fcb    = (const float*)d_in[12];
    float* out = (float*)d_out;

    const int* src = ei;
    const int* dst = ei + N_EDGES;

    const int NBLK = (N_NODES + 127) / 128;   // 391

    // weight prepass + zero (covers al/ar) + CSR build with parallel scan
    prep_w_kernel<<<(256 * 256 + 64 * 256 + 255) / 256, 256>>>(W1, W2);
    zero_kernel<<<(N_NODES * 4 + 255) / 256, 256>>>();
    hist_kernel<<<(N_EDGES + 255) / 256, 256>>>(dst);
    scan1_kernel<<<SCAN_BLOCKS, 1024>>>();
    scan2_kernel<<<1, 32>>>();
    scan3_kernel<<<SCAN_BLOCKS, 1024>>>();
    scatter_kernel<<<(N_EDGES + 255) / 256, 256>>>(src, dst);

    // Layer 1: tensor-core GEMM with fused attention dots, then aggregation
    dim3 grid1(NBLK, 4);
    gemm_mma_kernel<256><<<grid1, 256>>>(x, a_src1, a_dst1, N_NODES);
    aggregate1_kernel<<<(N_NODES + 7) / 8, 256>>>(b1);

    // Layer 2 (A = g_h1 selected inside the kernel; asrc2/adst2 are 64-wide)
    dim3 grid2(NBLK, 1);
    gemm_mma_kernel<64><<<grid2, 256>>>(nullptr, a_src2, a_dst2, N_NODES);
    aggregate2_kernel<<<(N_NODES + 7) / 8, 256>>>(b2, batch, out);

    // Pool + FC
    fc_kernel<<<1, 32>>>(fcW, fcb, out + (size_t)N_NODES * HID);
}